// round 14
// baseline (speedup 1.0000x reference)
#include <cuda_runtime.h>
#include <cstdint>

// Problem shapes (fixed by the dataset)
#define NUM_F 50000
#define KNBR  32
#define EMB   128
#define TF    64     // feeds per CTA
#define KC    32     // GEMM k-chunk

// Pre-transposed gate weight Wt[2E][E] (no allocation allowed -> device global)
__device__ float g_Wt[256 * 128];

typedef unsigned long long ull;

__device__ __forceinline__ ull rep2(float x) {
    ull r; asm("mov.b64 %0, {%1, %1};" : "=l"(r) : "f"(x)); return r;
}
__device__ __forceinline__ void fma2(ull& acc, ull a, ull b) {
    asm("fma.rn.f32x2 %0, %1, %2, %0;" : "+l"(acc) : "l"(a), "l"(b));
}
__device__ __forceinline__ void unpack2(float& lo, float& hi, ull v) {
    asm("mov.b64 {%0, %1}, %2;" : "=f"(lo), "=f"(hi) : "l"(v));
}
// Swizzled flat index into the transposed A tile (stride 68 floats per k-row).
// Conflict-free STS and 16B-aligned broadcast v2.b64 reads (verified mod-32).
__device__ __forceinline__ int aidx(int c, int r) {
    return c * 68 + (((r >> 2) ^ (((c >> 3) & 3) << 1)) << 2) + (r & 3);
}
__device__ __forceinline__ void half_bar(int h) {
    asm volatile("bar.sync %0, %1;" :: "r"(1 + h), "r"(128) : "memory");
}

// Dynamic shared memory layout. As (phase 2) aliases the phase-1 buffers.
struct SmemT {
    float aggS[TF][132];                 // 33792 B; CF in all access modes
    union {
        struct {
            float part[2][4][EMB];       // [half][warp][col] per-warp partials
            float alphaS[2][KNBR];       // [half][k] raw masked scores
        } p1;
        float As[KC * 68];               // phase-2 A tile (8704 B)
    };
};
#define SMEM_BYTES (sizeof(SmemT))

// ---------------------------------------------------------------------------
// Kernel T: transpose W [128][256] -> Wt [256][128] (tiny, once per launch)
// ---------------------------------------------------------------------------
__global__ void wt_kernel(const float* __restrict__ Wm)
{
    const int e = blockIdx.x;     // 0..127
    const int j = threadIdx.x;    // 0..255
    g_Wt[j * 128 + e] = Wm[e * 256 + j];
}

// ---------------------------------------------------------------------------
// Fused kernel, per CTA of 64 feeds:
//   Phase 1: gather + rank-1 attention softmax + aggregate -> aggS (SMEM).
//            Rows stay in registers; softmax is redundantly warp-parallel,
//            2 named barriers per feed; adjacency read as 2 uniform int4.
//   Phase 2: gate = sigmoid(cat([embf,agg]) @ W^T + b); out = g*embf+(1-g)*agg
// __launch_bounds__(256,2): 128-reg budget -> no spills in the FFMA2 loop.
// ---------------------------------------------------------------------------
__global__ void __launch_bounds__(256, 2) fused_kernel(
    const int* __restrict__ adj,
    const float* __restrict__ emb,
    const float* __restrict__ embf,
    const float* __restrict__ u,
    const float* __restrict__ bias,
    float* __restrict__ out)
{
    extern __shared__ char smem_raw[];
    SmemT& S = *reinterpret_cast<SmemT*>(smem_raw);

    const int tid  = threadIdx.x;
    const int f0   = blockIdx.x * TF;
    const int lane = tid & 31;

    // ---------------- Phase 1: attention aggregate (two 128-thread halves) ---
    {
        const int h    = tid >> 7;        // half-block id (0/1)
        const int htid = tid & 127;
        const int hw   = htid >> 5;       // warp within half (0..3)

        const float4 uv = reinterpret_cast<const float4*>(u)[lane];

        float4   v[8];                    // this warp's 8 k-rows x 4 cols
        unsigned mbits;                   // bit r: adjacency index != 0

        // Prologue: iteration 0's indices (2 uniform int4) + gathers (MLP=8)
        {
            int fglob = f0 + h * 32;
            if (fglob >= NUM_F) fglob = NUM_F - 1;
            const int4* ap = reinterpret_cast<const int4*>(
                adj + fglob * KNBR + hw * 8);
            const int4 a0 = ap[0], a1 = ap[1];
            int nidxs[8] = {a0.x, a0.y, a0.z, a0.w, a1.x, a1.y, a1.z, a1.w};
            mbits = 0u;
            #pragma unroll
            for (int r = 0; r < 8; r++)
                mbits |= (nidxs[r] != 0 ? 1u : 0u) << r;
            #pragma unroll
            for (int r = 0; r < 8; r++)
                v[r] = reinterpret_cast<const float4*>(
                    emb + (size_t)nidxs[r] * EMB)[lane];
        }

        #pragma unroll 1
        for (int i = 0; i < 32; i++) {
            const int fl = h * 32 + i;    // local feed row (0..63)

            // u-dot per k-row + warp reduce -> alphaS (masked raw scores)
            #pragma unroll
            for (int r = 0; r < 8; r++) {
                float p = v[r].x * uv.x + v[r].y * uv.y
                        + v[r].z * uv.z + v[r].w * uv.w;
                #pragma unroll
                for (int o = 16; o; o >>= 1)
                    p += __shfl_xor_sync(0xffffffffu, p, o);
                if (lane == 0)
                    S.p1.alphaS[h][hw * 8 + r] =
                        ((mbits >> r) & 1u) ? p : (p - 10000.0f);
            }

            // Prefetch next iteration's indices (registers only, 2 x int4)
            int      nidxs[8];
            unsigned nmbits = 0u;
            if (i < 31) {
                int fglob = f0 + fl + 1;
                if (fglob >= NUM_F) fglob = NUM_F - 1;
                const int4* ap = reinterpret_cast<const int4*>(
                    adj + fglob * KNBR + hw * 8);
                const int4 a0 = ap[0], a1 = ap[1];
                nidxs[0] = a0.x; nidxs[1] = a0.y; nidxs[2] = a0.z; nidxs[3] = a0.w;
                nidxs[4] = a1.x; nidxs[5] = a1.y; nidxs[6] = a1.z; nidxs[7] = a1.w;
                #pragma unroll
                for (int r = 0; r < 8; r++)
                    nmbits |= (nidxs[r] != 0 ? 1u : 0u) << r;
            }

            half_bar(h);                  // bar1: alphaS complete

            // Redundant warp-parallel softmax: each warp reduces all 32 scores
            float wgt;
            {
                const float a = S.p1.alphaS[h][lane];   // CF 32-wide LDS
                float m = a;
                #pragma unroll
                for (int o = 16; o; o >>= 1)
                    m = fmaxf(m, __shfl_xor_sync(0xffffffffu, m, o));
                float e = __expf(a - m);
                float s = e;
                #pragma unroll
                for (int o = 16; o; o >>= 1)
                    s += __shfl_xor_sync(0xffffffffu, s, o);
                wgt = __fdividef(e, s);   // lane l holds weight for k = l
            }

            // Per-warp register partial over this warp's 8 k-rows; weights
            // pulled from the softmax lanes via shuffle (no smem write-back)
            float4 part = make_float4(0.f, 0.f, 0.f, 0.f);
            #pragma unroll
            for (int r = 0; r < 8; r++) {
                const float a = __shfl_sync(0xffffffffu, wgt, hw * 8 + r);
                part.x = fmaf(a, v[r].x, part.x);
                part.y = fmaf(a, v[r].y, part.y);
                part.z = fmaf(a, v[r].z, part.z);
                part.w = fmaf(a, v[r].w, part.w);
            }
            *reinterpret_cast<float4*>(&S.p1.part[h][hw][lane * 4]) = part;

            // v consumed -> issue next gathers now (overlap barP + combine)
            if (i < 31) {
                #pragma unroll
                for (int r = 0; r < 8; r++)
                    v[r] = reinterpret_cast<const float4*>(
                        emb + (size_t)nidxs[r] * EMB)[lane];
                mbits = nmbits;
            }

            half_bar(h);                  // barP: partials complete

            // 4-way combine -> aggS row
            const float s = S.p1.part[h][0][htid] + S.p1.part[h][1][htid]
                          + S.p1.part[h][2][htid] + S.p1.part[h][3][htid];
            S.aggS[fl][htid] = s;
            // Ordering audit: alphaS(i) reads in (bar1(i), barP(i)); alphaS(i+1)
            // writes after barP(i). part(i) reads precede bar1(i+1); part(i+1)
            // writes follow bar1(i+1). Both safe without parity buffers.
        }
    }
    __syncthreads();   // phase boundary: aggS complete, p1 region reusable

    // ---------------- Phase 2: gated-fusion GEMM --------------------------
    const int e0 = (tid & 31) * 4;        // 4 output columns per thread
    const int fr = (tid >> 5) * 8;        // 8 feed rows per thread (warp-uniform)

    // A-tile loader coordinates
    const int lr  = tid >> 2;             // tile row (0..63)
    const int lc0 = (tid & 3) * 8;        // first of 8 k-cols
    int fg = f0 + lr;
    if (fg >= NUM_F) fg = NUM_F - 1;

    ull acc[4][4];
    #pragma unroll
    for (int p = 0; p < 4; p++)
        #pragma unroll
        for (int e = 0; e < 4; e++)
            acc[p][e] = 0ull;

    // Prefetch chunk 0 (embf)
    float4 pf0, pf1;
    {
        const float* g = embf + (size_t)fg * EMB + lc0;
        pf0 = *reinterpret_cast<const float4*>(g);
        pf1 = *reinterpret_cast<const float4*>(g + 4);
    }

    #pragma unroll 1
    for (int chunk = 0; chunk < 8; chunk++) {
        const int j0 = chunk * KC;

        // Store prefetched fragment transposed+swizzled into As
        S.As[aidx(lc0 + 0, lr)] = pf0.x;  S.As[aidx(lc0 + 1, lr)] = pf0.y;
        S.As[aidx(lc0 + 2, lr)] = pf0.z;  S.As[aidx(lc0 + 3, lr)] = pf0.w;
        S.As[aidx(lc0 + 4, lr)] = pf1.x;  S.As[aidx(lc0 + 5, lr)] = pf1.y;
        S.As[aidx(lc0 + 6, lr)] = pf1.z;  S.As[aidx(lc0 + 7, lr)] = pf1.w;
        __syncthreads();

        // Prefetch next chunk: embf from GMEM, agg from SMEM aggS
        {
            const int nc = (chunk < 7) ? (chunk + 1) : 7;
            if (nc < 4) {
                const float* g = embf + (size_t)fg * EMB + nc * KC + lc0;
                pf0 = *reinterpret_cast<const float4*>(g);
                pf1 = *reinterpret_cast<const float4*>(g + 4);
            } else {
                const float* g = &S.aggS[lr][(nc - 4) * KC + lc0];
                pf0 = *reinterpret_cast<const float4*>(g);
                pf1 = *reinterpret_cast<const float4*>(g + 4);
            }
        }

        #pragma unroll
        for (int jc = 0; jc < KC; jc++) {
            const float4 wv = *reinterpret_cast<const float4*>(
                g_Wt + (size_t)(j0 + jc) * EMB + e0);
            ull w[4];
            w[0] = rep2(wv.x); w[1] = rep2(wv.y);
            w[2] = rep2(wv.z); w[3] = rep2(wv.w);
            const ulonglong2 aA =
                *reinterpret_cast<const ulonglong2*>(&S.As[aidx(jc, fr)]);
            const ulonglong2 aB =
                *reinterpret_cast<const ulonglong2*>(&S.As[aidx(jc, fr + 4)]);
            ull ap[4] = {aA.x, aA.y, aB.x, aB.y};
            #pragma unroll
            for (int p = 0; p < 4; p++)
                #pragma unroll
                for (int e = 0; e < 4; e++)
                    fma2(acc[p][e], ap[p], w[e]);
        }
        __syncthreads();   // readers done before next chunk's stores
    }

    // Epilogue: bias + sigmoid gate + blend (agg read from SMEM)
    const float4 bv = *reinterpret_cast<const float4*>(bias + e0);
    #pragma unroll
    for (int p = 0; p < 4; p++) {
        float xlo[4], xhi[4];
        #pragma unroll
        for (int e = 0; e < 4; e++)
            unpack2(xlo[e], xhi[e], acc[p][e]);

        #pragma unroll
        for (int hh = 0; hh < 2; hh++) {
            const int fl = fr + 2 * p + hh;
            const int f  = f0 + fl;
            if (f >= NUM_F) continue;
            const float* x = hh ? xhi : xlo;
            const float4 ef = *reinterpret_cast<const float4*>(
                embf + (size_t)f * EMB + e0);
            const float4 ag = *reinterpret_cast<const float4*>(&S.aggS[fl][e0]);
            const float g0 = 1.0f / (1.0f + __expf(-(x[0] + bv.x)));
            const float g1 = 1.0f / (1.0f + __expf(-(x[1] + bv.y)));
            const float g2 = 1.0f / (1.0f + __expf(-(x[2] + bv.z)));
            const float g3 = 1.0f / (1.0f + __expf(-(x[3] + bv.w)));
            float4 o;
            o.x = g0 * ef.x + (1.0f - g0) * ag.x;
            o.y = g1 * ef.y + (1.0f - g1) * ag.y;
            o.z = g2 * ef.z + (1.0f - g2) * ag.z;
            o.w = g3 * ef.w + (1.0f - g3) * ag.w;
            *reinterpret_cast<float4*>(out + (size_t)f * EMB + e0) = o;
        }
    }
}

extern "C" void kernel_launch(void* const* d_in, const int* in_sizes, int n_in,
                              void* d_out, int out_size)
{
    const int*   adj  = (const int*)d_in[0];          // [F, 32] int32
    const float* emb  = (const float*)d_in[1];        // [100000, 128]
    const float* embf = (const float*)d_in[2];        // [F, 128]
    const float* u    = (const float*)d_in[3];        // [128, 1]
    const float* Wm   = (const float*)d_in[4];        // [128, 256]
    const float* bias = (const float*)d_in[5];        // [128]
    float* out = (float*)d_out;                       // [F, 128]

    (void)in_sizes; (void)n_in; (void)out_size;

    // Opt into >48KB dynamic smem (idempotent, immediate API; capture-safe).
    (void)cudaFuncSetAttribute(fused_kernel,
                               cudaFuncAttributeMaxDynamicSharedMemorySize,
                               (int)SMEM_BYTES);

    wt_kernel<<<128, 256>>>(Wm);
    fused_kernel<<<(NUM_F + TF - 1) / TF, 256, SMEM_BYTES>>>(
        adj, emb, embf, u, bias, out);
}

// round 15
// speedup vs baseline: 1.3906x; 1.3906x over previous
#include <cuda_runtime.h>
#include <cstdint>

// Problem shapes (fixed by the dataset)
#define NUM_F 50000
#define KNBR  32
#define EMB   128
#define TF    64     // feeds per CTA
#define KC    32     // GEMM k-chunk

// Pre-transposed gate weight Wt[2E][E] (no allocation allowed -> device global)
__device__ float g_Wt[256 * 128];

typedef unsigned long long ull;

__device__ __forceinline__ ull rep2(float x) {
    ull r; asm("mov.b64 %0, {%1, %1};" : "=l"(r) : "f"(x)); return r;
}
__device__ __forceinline__ void fma2(ull& acc, ull a, ull b) {
    asm("fma.rn.f32x2 %0, %1, %2, %0;" : "+l"(acc) : "l"(a), "l"(b));
}
__device__ __forceinline__ void unpack2(float& lo, float& hi, ull v) {
    asm("mov.b64 {%0, %1}, %2;" : "=f"(lo), "=f"(hi) : "l"(v));
}
// Swizzled flat index into the transposed A tile (stride 68 floats per k-row).
// Conflict-free STS and 16B-aligned broadcast v2.b64 reads (verified mod-32).
__device__ __forceinline__ int aidx(int c, int r) {
    return c * 68 + (((r >> 2) ^ (((c >> 3) & 3) << 1)) << 2) + (r & 3);
}

// Dynamic shared memory layout. As (phase 2) overlaps nothing in phase 1 now.
struct SmemT {
    float aggS[TF][132];                 // 33792 B; CF in all access modes
    float As[KC * 68];                   // phase-2 A tile (8704 B)
};
#define SMEM_BYTES (sizeof(SmemT))

// ---------------------------------------------------------------------------
// Kernel T: transpose W [128][256] -> Wt [256][128] (tiny, once per launch)
// ---------------------------------------------------------------------------
__global__ void wt_kernel(const float* __restrict__ Wm)
{
    const int e = blockIdx.x;     // 0..127
    const int j = threadIdx.x;    // 0..255
    g_Wt[j * 128 + e] = Wm[e * 256 + j];
}

// ---------------------------------------------------------------------------
// Fused kernel, per CTA of 64 feeds:
//   Phase 1: WARP-INDEPENDENT online-softmax attention aggregate -> aggS.
//            Each warp owns 8 feeds; 32 neighbors in 4 chunks of 8 with
//            running (m, s, acc). No named barriers, no smem exchange.
//   Phase 2: gate = sigmoid(cat([embf,agg]) @ W^T + b); out = g*embf+(1-g)*agg
// __launch_bounds__(256,3): occ 3 for latency hiding (measured: latency-bound).
// ---------------------------------------------------------------------------
__global__ void __launch_bounds__(256, 3) fused_kernel(
    const int* __restrict__ adj,
    const float* __restrict__ emb,
    const float* __restrict__ embf,
    const float* __restrict__ u,
    const float* __restrict__ bias,
    float* __restrict__ out)
{
    extern __shared__ char smem_raw[];
    SmemT& S = *reinterpret_cast<SmemT*>(smem_raw);

    const int tid  = threadIdx.x;
    const int f0   = blockIdx.x * TF;
    const int lane = tid & 31;
    const int w    = tid >> 5;            // warp id (0..7)

    // ---------------- Phase 1: warp-independent online-softmax --------------
    {
        const float4 uv = reinterpret_cast<const float4*>(u)[lane];

        #pragma unroll 1
        for (int j = 0; j < 8; j++) {
            const int fl = w * 8 + j;     // local feed row (0..63)
            int fglob = f0 + fl;
            if (fglob >= NUM_F) fglob = NUM_F - 1;   // clamp; output guarded
            const int* arow = adj + fglob * KNBR;

            float  m    = -1e30f;
            float  ssum = 0.0f;
            float4 acc  = make_float4(0.f, 0.f, 0.f, 0.f);

            #pragma unroll 1
            for (int c = 0; c < 4; c++) {
                // 8 neighbor indices: 2 uniform int4 loads (32B-aligned)
                const int4* ap = reinterpret_cast<const int4*>(arow + c * 8);
                const int4 a0 = ap[0], a1 = ap[1];
                const int idx[8] = {a0.x, a0.y, a0.z, a0.w,
                                    a1.x, a1.y, a1.z, a1.w};

                // Batched coalesced gathers (MLP=8), rows stay in registers
                float4 v[8];
                #pragma unroll
                for (int r = 0; r < 8; r++)
                    v[r] = reinterpret_cast<const float4*>(
                        emb + (size_t)idx[r] * EMB)[lane];

                // Scores: 4-col partial dot + full XOR butterfly (result in
                // ALL lanes), then additive padding mask
                float p[8];
                #pragma unroll
                for (int r = 0; r < 8; r++) {
                    float t = v[r].x * uv.x + v[r].y * uv.y
                            + v[r].z * uv.z + v[r].w * uv.w;
                    #pragma unroll
                    for (int o = 16; o; o >>= 1)
                        t += __shfl_xor_sync(0xffffffffu, t, o);
                    p[r] = t + (idx[r] != 0 ? 0.0f : -10000.0f);
                }

                // Online softmax update
                float mc = p[0];
                #pragma unroll
                for (int r = 1; r < 8; r++) mc = fmaxf(mc, p[r]);
                const float mn    = fmaxf(m, mc);
                const float scale = __expf(m - mn);   // 0 on first chunk
                ssum *= scale;
                acc.x *= scale; acc.y *= scale;
                acc.z *= scale; acc.w *= scale;
                #pragma unroll
                for (int r = 0; r < 8; r++) {
                    const float e = __expf(p[r] - mn);
                    ssum += e;
                    acc.x = fmaf(e, v[r].x, acc.x);
                    acc.y = fmaf(e, v[r].y, acc.y);
                    acc.z = fmaf(e, v[r].z, acc.z);
                    acc.w = fmaf(e, v[r].w, acc.w);
                }
                m = mn;
            }

            const float inv = __fdividef(1.0f, ssum);
            float4 o;
            o.x = acc.x * inv; o.y = acc.y * inv;
            o.z = acc.z * inv; o.w = acc.w * inv;
            *reinterpret_cast<float4*>(&S.aggS[fl][lane * 4]) = o;
        }
    }
    __syncthreads();   // phase boundary: aggS complete

    // ---------------- Phase 2: gated-fusion GEMM --------------------------
    const int e0 = (tid & 31) * 4;        // 4 output columns per thread
    const int fr = (tid >> 5) * 8;        // 8 feed rows per thread (warp-uniform)

    // A-tile loader coordinates
    const int lr  = tid >> 2;             // tile row (0..63)
    const int lc0 = (tid & 3) * 8;        // first of 8 k-cols
    int fg = f0 + lr;
    if (fg >= NUM_F) fg = NUM_F - 1;

    ull acc[4][4];
    #pragma unroll
    for (int p = 0; p < 4; p++)
        #pragma unroll
        for (int e = 0; e < 4; e++)
            acc[p][e] = 0ull;

    // Prefetch chunk 0 (embf)
    float4 pf0, pf1;
    {
        const float* g = embf + (size_t)fg * EMB + lc0;
        pf0 = *reinterpret_cast<const float4*>(g);
        pf1 = *reinterpret_cast<const float4*>(g + 4);
    }

    #pragma unroll 1
    for (int chunk = 0; chunk < 8; chunk++) {
        const int j0 = chunk * KC;

        // Store prefetched fragment transposed+swizzled into As
        S.As[aidx(lc0 + 0, lr)] = pf0.x;  S.As[aidx(lc0 + 1, lr)] = pf0.y;
        S.As[aidx(lc0 + 2, lr)] = pf0.z;  S.As[aidx(lc0 + 3, lr)] = pf0.w;
        S.As[aidx(lc0 + 4, lr)] = pf1.x;  S.As[aidx(lc0 + 5, lr)] = pf1.y;
        S.As[aidx(lc0 + 6, lr)] = pf1.z;  S.As[aidx(lc0 + 7, lr)] = pf1.w;
        __syncthreads();

        // Prefetch next chunk: embf from GMEM, agg from SMEM aggS
        {
            const int nc = (chunk < 7) ? (chunk + 1) : 7;
            if (nc < 4) {
                const float* g = embf + (size_t)fg * EMB + nc * KC + lc0;
                pf0 = *reinterpret_cast<const float4*>(g);
                pf1 = *reinterpret_cast<const float4*>(g + 4);
            } else {
                const float* g = &S.aggS[lr][(nc - 4) * KC + lc0];
                pf0 = *reinterpret_cast<const float4*>(g);
                pf1 = *reinterpret_cast<const float4*>(g + 4);
            }
        }

        #pragma unroll
        for (int jc = 0; jc < KC; jc++) {
            const float4 wv = *reinterpret_cast<const float4*>(
                g_Wt + (size_t)(j0 + jc) * EMB + e0);
            ull wr[4];
            wr[0] = rep2(wv.x); wr[1] = rep2(wv.y);
            wr[2] = rep2(wv.z); wr[3] = rep2(wv.w);
            const ulonglong2 aA =
                *reinterpret_cast<const ulonglong2*>(&S.As[aidx(jc, fr)]);
            const ulonglong2 aB =
                *reinterpret_cast<const ulonglong2*>(&S.As[aidx(jc, fr + 4)]);
            ull ap[4] = {aA.x, aA.y, aB.x, aB.y};
            #pragma unroll
            for (int p = 0; p < 4; p++)
                #pragma unroll
                for (int e = 0; e < 4; e++)
                    fma2(acc[p][e], ap[p], wr[e]);
        }
        __syncthreads();   // readers done before next chunk's stores
    }

    // Epilogue: bias + sigmoid gate + blend (agg read from SMEM)
    const float4 bv = *reinterpret_cast<const float4*>(bias + e0);
    #pragma unroll
    for (int p = 0; p < 4; p++) {
        float xlo[4], xhi[4];
        #pragma unroll
        for (int e = 0; e < 4; e++)
            unpack2(xlo[e], xhi[e], acc[p][e]);

        #pragma unroll
        for (int hh = 0; hh < 2; hh++) {
            const int fl = fr + 2 * p + hh;
            const int f  = f0 + fl;
            if (f >= NUM_F) continue;
            const float* x = hh ? xhi : xlo;
            const float4 ef = *reinterpret_cast<const float4*>(
                embf + (size_t)f * EMB + e0);
            const float4 ag = *reinterpret_cast<const float4*>(&S.aggS[fl][e0]);
            const float g0 = 1.0f / (1.0f + __expf(-(x[0] + bv.x)));
            const float g1 = 1.0f / (1.0f + __expf(-(x[1] + bv.y)));
            const float g2 = 1.0f / (1.0f + __expf(-(x[2] + bv.z)));
            const float g3 = 1.0f / (1.0f + __expf(-(x[3] + bv.w)));
            float4 o;
            o.x = g0 * ef.x + (1.0f - g0) * ag.x;
            o.y = g1 * ef.y + (1.0f - g1) * ag.y;
            o.z = g2 * ef.z + (1.0f - g2) * ag.z;
            o.w = g3 * ef.w + (1.0f - g3) * ag.w;
            *reinterpret_cast<float4*>(out + (size_t)f * EMB + e0) = o;
        }
    }
}

extern "C" void kernel_launch(void* const* d_in, const int* in_sizes, int n_in,
                              void* d_out, int out_size)
{
    const int*   adj  = (const int*)d_in[0];          // [F, 32] int32
    const float* emb  = (const float*)d_in[1];        // [100000, 128]
    const float* embf = (const float*)d_in[2];        // [F, 128]
    const float* u    = (const float*)d_in[3];        // [128, 1]
    const float* Wm   = (const float*)d_in[4];        // [128, 256]
    const float* bias = (const float*)d_in[5];        // [128]
    float* out = (float*)d_out;                       // [F, 128]

    (void)in_sizes; (void)n_in; (void)out_size;

    // Opt into >48KB dynamic smem (idempotent, immediate API; capture-safe).
    (void)cudaFuncSetAttribute(fused_kernel,
                               cudaFuncAttributeMaxDynamicSharedMemorySize,
                               (int)SMEM_BYTES);

    wt_kernel<<<128, 256>>>(Wm);
    fused_kernel<<<(NUM_F + TF - 1) / TF, 256, SMEM_BYTES>>>(
        adj, emb, embf, u, bias, out);
}